// round 16
// baseline (speedup 1.0000x reference)
#include <cuda_runtime.h>
#include <cuda_bf16.h>
#include <math.h>

// S4D kernel init via warp-level TF32 mma.sync (baseline PTX, compute_103).
// out[h, j*128+i] = D[j,i] of D[32x128] = A[32x64] * B[64x128],
//   K channels: k=n -> (A=Px, B=Qr); k=32+n -> (A=-Py, B=Qi).
// Single-pass pure TF32 (rel_err ~2.2e-4, threshold 1e-3).
//
// Round-15: pairwise k-permutation phys(k) = (k&~7)|((k&3)<<1)|((k>>2)&1)
// makes each mma fragment's {t, t+4} pair adjacent -> every fragment load is
// ONE LDS.64. With QP=72 (mod 32 = 8) the 64-bit phases are bank-exact
// (bank = 8g+2t, distinct per 16-lane phase). Mainloop shared-pipe
// instructions: 512 -> 256 per block; address ALU halves too.

#define NTH 128
#define N2  32
#define TT  128
#define QP  72          // smem row pitch (words); QP mod 32 = 8

typedef unsigned int u32;

// dynamic smem layout (32-bit word offsets)
#define OFF_Q    0                      // u32 tf32 [128][QP]
#define OFF_PH   (OFF_Q  + TT * QP)     // u32 tf32 [32][QP]
#define OFF_POW  (OFF_PH + N2 * QP)     // float2 [32][12]
#define OFF_CCF  (OFF_POW + N2 * 24)    // float2 [32]
#define SMEM_W   (OFF_CCF + 64)
#define SMEM_B   (SMEM_W * 4)           // 49408 B

__device__ __forceinline__ int kphys(int n) {   // n in 0..31 (block bits kept)
    return ((n >> 3) << 3) | ((n & 3) << 1) | ((n >> 2) & 1);
}
__device__ __forceinline__ float2 cmul(float2 a, float2 b) {
    return make_float2(a.x * b.x - a.y * b.y, a.x * b.y + a.y * b.x);
}
__device__ __forceinline__ u32 tf32_hi(float x) {
    u32 t; asm("cvt.rna.tf32.f32 %0, %1;" : "=r"(t) : "f"(x)); return t;
}
__device__ __forceinline__ void mma_tf32(float* c, u32 a0, u32 a1, u32 a2, u32 a3,
                                         u32 b0, u32 b1) {
    asm volatile(
        "mma.sync.aligned.m16n8k8.row.col.f32.tf32.tf32.f32 "
        "{%0,%1,%2,%3}, {%4,%5,%6,%7}, {%8,%9}, {%0,%1,%2,%3};"
        : "+f"(c[0]), "+f"(c[1]), "+f"(c[2]), "+f"(c[3])
        : "r"(a0), "r"(a1), "r"(a2), "r"(a3), "r"(b0), "r"(b1));
}

__global__ __launch_bounds__(NTH)
void s4d_mma_kernel(
    const float* __restrict__ log_dt,
    const float* __restrict__ C,          // (H, 32, 2)
    const float* __restrict__ lAr,        // (H, 32)
    const float* __restrict__ Aim,        // (H, 32)
    float* __restrict__ out,              // (H, L)
    int L)
{
    extern __shared__ u32 smw[];
    u32*    sQ   = smw + OFF_Q;          // [i][phys k]
    u32*    sPh  = smw + OFF_PH;         // [j][phys k]
    float2* sPow = (float2*)(smw + OFF_POW);
    float2* sCcf = (float2*)(smw + OFF_CCF);

    const int h = blockIdx.x, tid = threadIdx.x;
    const int wid = tid >> 5, lane = tid & 31;
    const int g = lane >> 2, t = lane & 3;      // mma quad coords

    // ---------- Phase 0: per-n coefficients + power table ----------
    if (tid < N2) {
        const int n = tid, gg = h * N2 + n;
        float dt  = expf(log_dt[h]);
        float ar0 = -expf(lAr[gg]);
        float ai0 = Aim[gg];
        float e = expf(ar0 * dt), s, c;
        sincosf(ai0 * dt, &s, &c);
        float2 z = make_float2(e * c, e * s);   // w = exp(dtA)
        #pragma unroll
        for (int k = 0; k < 12; k++) {
            sPow[n * 12 + k] = z;
            z = make_float2(z.x * z.x - z.y * z.y, 2.0f * z.x * z.y);
        }
        float2 w0 = sPow[n * 12];
        float Er = w0.x - 1.0f, Ei = w0.y;
        float inv = 1.0f / (ar0 * ar0 + ai0 * ai0);
        float Dr = (Er * ar0 + Ei * ai0) * inv;
        float Di = (Ei * ar0 - Er * ai0) * inv;
        float cr = C[2 * gg], ci = C[2 * gg + 1];
        sCcf[n] = make_float2(2.0f * (cr * Dr - ci * Di),
                              2.0f * (cr * Di + ci * Dr));
    }
    __syncthreads();

    // ---------- Q: recurrence, thread (n=lane, seg=wid), permuted k ----------
    {
        const int n = lane, seg = wid;           // 4 segs of 32 i
        const int pn = kphys(n);                 // bijection -> conflict-free STS
        float2 z = sCcf[n];
        if (seg & 1) z = cmul(z, sPow[n * 12 + 5]);   // w^32
        if (seg & 2) z = cmul(z, sPow[n * 12 + 6]);   // w^64
        float2 w = sPow[n * 12];
        #pragma unroll
        for (int k = 0; k < 32; k++) {
            int i = seg * 32 + k;
            sQ[i * QP + pn]      = tf32_hi(z.x); // Qr at k=n
            sQ[i * QP + pn + 32] = tf32_hi(z.y); // Qi at k=32+n
            z = cmul(z, w);
        }
    }
    // ---------- P: w^(128j), permuted k ----------
    #pragma unroll
    for (int r = 0; r < 8; r++) {
        int idx = r * NTH + tid;
        int n = idx & 31, j = idx >> 5;          // j = r*4 + wid
        float2 z = make_float2(1.0f, 0.0f);
        if (j & 1)  z = cmul(z, sPow[n * 12 + 7]);
        if (j & 2)  z = cmul(z, sPow[n * 12 + 8]);
        if (j & 4)  z = cmul(z, sPow[n * 12 + 9]);
        if (j & 8)  z = cmul(z, sPow[n * 12 + 10]);
        if (j & 16) z = cmul(z, sPow[n * 12 + 11]);
        const int pn = kphys(n);
        sPh[j * QP + pn]      = tf32_hi(z.x);    // Px
        sPh[j * QP + pn + 32] = tf32_hi(-z.y);   // -Py
    }
    __syncthreads();

    // ---------- Mainloop: warp w covers i in [32w, 32w+32) = 4 n-tiles ----------
    float acc[2][4][4];
    #pragma unroll
    for (int mt = 0; mt < 2; mt++)
        #pragma unroll
        for (int nt = 0; nt < 4; nt++)
            #pragma unroll
            for (int c = 0; c < 4; c++) acc[mt][nt][c] = 0.0f;

    #pragma unroll
    for (int ks = 0; ks < 8; ks++) {
        const int kb = 8 * ks + 2 * t;           // phys cols {2t, 2t+1} = k {t, t+4}
        // A fragments (P): one LDS.64 per row-group, bank-exact
        uint2 a0[2], a1[2];
        #pragma unroll
        for (int mt = 0; mt < 2; mt++) {
            a0[mt] = *(const uint2*)&sPh[(16 * mt + g)     * QP + kb];
            a1[mt] = *(const uint2*)&sPh[(16 * mt + g + 8) * QP + kb];
        }
        // B fragments (Q): one LDS.64 per n-tile
        uint2 b[4];
        #pragma unroll
        for (int nt = 0; nt < 4; nt++)
            b[nt] = *(const uint2*)&sQ[(32 * wid + 8 * nt + g) * QP + kb];

        #pragma unroll
        for (int mt = 0; mt < 2; mt++)
            #pragma unroll
            for (int nt = 0; nt < 4; nt++)
                mma_tf32(acc[mt][nt],
                         a0[mt].x, a1[mt].x, a0[mt].y, a1[mt].y,
                         b[nt].x, b[nt].y);
    }

    // ---------- Epilogue: D[j,i] -> out[h, j*128 + i], float2 stores ----------
    float* op = out + (size_t)h * (size_t)L;
    #pragma unroll
    for (int mt = 0; mt < 2; mt++) {
        #pragma unroll
        for (int nt = 0; nt < 4; nt++) {
            int j0 = 16 * mt + g;
            int i0 = 32 * wid + 8 * nt + 2 * t;
            *(float2*)&op[j0 * TT + i0]       = make_float2(acc[mt][nt][0], acc[mt][nt][1]);
            *(float2*)&op[(j0 + 8) * TT + i0] = make_float2(acc[mt][nt][2], acc[mt][nt][3]);
        }
    }
}

extern "C" void kernel_launch(void* const* d_in, const int* in_sizes, int n_in,
                              void* d_out, int out_size) {
    // inputs: [0]=L (scalar), [1]=log_dt (H), [2]=C (H,32,2),
    //         [3]=log_A_real (H,32), [4]=A_imag (H,32)
    const float* log_dt = (const float*)d_in[1];
    const float* C      = (const float*)d_in[2];
    const float* lAr    = (const float*)d_in[3];
    const float* Aim    = (const float*)d_in[4];
    float* out = (float*)d_out;

    int H = in_sizes[1];          // 1024
    int L = out_size / H;         // 4096

    cudaFuncSetAttribute(s4d_mma_kernel,
                         cudaFuncAttributeMaxDynamicSharedMemorySize, SMEM_B);
    s4d_mma_kernel<<<H, NTH, SMEM_B>>>(log_dt, C, lAr, Aim, out, L);
}

// round 17
// speedup vs baseline: 1.0022x; 1.0022x over previous
#include <cuda_runtime.h>
#include <cuda_bf16.h>
#include <math.h>

// S4D kernel init via warp-level TF32 mma.sync (baseline PTX, compute_103).
// out[h, j*128+i] = D[j,i] of D[32x128] = A[32x64] * B[64x128],
//   K channels: k=n -> (A=Px, B=Qr); k=32+n -> (A=-Py, B=Qi).
// Single-pass pure TF32 numerics (rel_err ~2.2e-4, threshold 1e-3).
//
// Round-16: K split into 2 passes (real channels, then imag channels) with
// accumulators persisting in registers. Q tile shrinks [128][68]->[128][36]
// (one component at a time; recurrence re-run per pass), smem 46.8->30.5KB,
// residency 3-4 -> 7 CTAs/SM (occ 21% -> ~44%) so the additive LDS/ALU/
// tensor phases can finally overlap across warps. Fragment/store bank
// patterns identical to the validated round-14 layout (pitch mod 32 = 4).

#define NTH 128
#define N2  32
#define TT  128
#define QQ  36          // Q pitch (words), 36 mod 32 = 4
#define QP  68          // P pitch (words), 68 mod 32 = 4

typedef unsigned int u32;

// dynamic smem layout (32-bit word offsets)
#define OFF_Q    0                      // u32 tf32 [128][QQ]   (one component)
#define OFF_P    (OFF_Q  + TT * QQ)     // u32 tf32 [32][QP]    (Px | -Py)
#define OFF_POW  (OFF_P  + N2 * QP)     // float2 [32][12]
#define OFF_CCF  (OFF_POW + N2 * 24)    // float2 [32]
#define SMEM_W   (OFF_CCF + 64)
#define SMEM_B   (SMEM_W * 4)           // 30464 B

__device__ __forceinline__ float2 cmul(float2 a, float2 b) {
    return make_float2(a.x * b.x - a.y * b.y, a.x * b.y + a.y * b.x);
}
__device__ __forceinline__ u32 tf32_hi(float x) {
    u32 t; asm("cvt.rna.tf32.f32 %0, %1;" : "=r"(t) : "f"(x)); return t;
}
__device__ __forceinline__ void mma_tf32(float* c, const u32* a, const u32* b) {
    asm volatile(
        "mma.sync.aligned.m16n8k8.row.col.f32.tf32.tf32.f32 "
        "{%0,%1,%2,%3}, {%4,%5,%6,%7}, {%8,%9}, {%0,%1,%2,%3};"
        : "+f"(c[0]), "+f"(c[1]), "+f"(c[2]), "+f"(c[3])
        : "r"(a[0]), "r"(a[1]), "r"(a[2]), "r"(a[3]), "r"(b[0]), "r"(b[1]));
}

__global__ __launch_bounds__(NTH)
void s4d_mma_kernel(
    const float* __restrict__ log_dt,
    const float* __restrict__ C,          // (H, 32, 2)
    const float* __restrict__ lAr,        // (H, 32)
    const float* __restrict__ Aim,        // (H, 32)
    float* __restrict__ out,              // (H, L)
    int L)
{
    extern __shared__ u32 smw[];
    u32*    sQ   = smw + OFF_Q;          // [i][n] one component per pass
    u32*    sP   = smw + OFF_P;          // [j][n] = Px, [j][n+32] = -Py
    float2* sPow = (float2*)(smw + OFF_POW);
    float2* sCcf = (float2*)(smw + OFF_CCF);

    const int h = blockIdx.x, tid = threadIdx.x;
    const int wid = tid >> 5, lane = tid & 31;
    const int g = lane >> 2, t = lane & 3;      // mma quad coords

    // ---------- Phase 0: per-n coefficients + power table ----------
    if (tid < N2) {
        const int n = tid, gg = h * N2 + n;
        float dt  = expf(log_dt[h]);
        float ar0 = -expf(lAr[gg]);
        float ai0 = Aim[gg];
        float e = expf(ar0 * dt), s, c;
        sincosf(ai0 * dt, &s, &c);
        float2 z = make_float2(e * c, e * s);   // w = exp(dtA)
        #pragma unroll
        for (int k = 0; k < 12; k++) {
            sPow[n * 12 + k] = z;
            z = make_float2(z.x * z.x - z.y * z.y, 2.0f * z.x * z.y);
        }
        float2 w0 = sPow[n * 12];
        float Er = w0.x - 1.0f, Ei = w0.y;
        float inv = 1.0f / (ar0 * ar0 + ai0 * ai0);
        float Dr = (Er * ar0 + Ei * ai0) * inv;
        float Di = (Ei * ar0 - Er * ai0) * inv;
        float cr = C[2 * gg], ci = C[2 * gg + 1];
        sCcf[n] = make_float2(2.0f * (cr * Dr - ci * Di),
                              2.0f * (cr * Di + ci * Dr));
    }
    __syncthreads();

    // ---------- P: w^(128j), both components, built once ----------
    #pragma unroll
    for (int r = 0; r < 8; r++) {
        int idx = r * NTH + tid;
        int n = idx & 31, j = idx >> 5;          // j = r*4 + wid
        float2 z = make_float2(1.0f, 0.0f);
        if (j & 1)  z = cmul(z, sPow[n * 12 + 7]);
        if (j & 2)  z = cmul(z, sPow[n * 12 + 8]);
        if (j & 4)  z = cmul(z, sPow[n * 12 + 9]);
        if (j & 8)  z = cmul(z, sPow[n * 12 + 10]);
        if (j & 16) z = cmul(z, sPow[n * 12 + 11]);
        sP[j * QP + n]      = tf32_hi(z.x);      // Px
        sP[j * QP + n + 32] = tf32_hi(-z.y);     // -Py
    }

    // ---------- Accumulators persist across both K passes ----------
    float acc[2][4][4];
    #pragma unroll
    for (int mt = 0; mt < 2; mt++)
        #pragma unroll
        for (int nt = 0; nt < 4; nt++)
            #pragma unroll
            for (int c = 0; c < 4; c++) acc[mt][nt][c] = 0.0f;

    #pragma unroll
    for (int pass = 0; pass < 2; pass++) {
        // ----- Q build: recurrence (n=lane, seg=wid), store ONE component -----
        {
            const int n = lane, seg = wid;       // 4 segs of 32 i
            float2 z = sCcf[n];
            if (seg & 1) z = cmul(z, sPow[n * 12 + 5]);   // w^32
            if (seg & 2) z = cmul(z, sPow[n * 12 + 6]);   // w^64
            float2 w = sPow[n * 12];
            #pragma unroll
            for (int k = 0; k < 32; k++) {
                int i = seg * 32 + k;
                sQ[i * QQ + n] = tf32_hi(pass == 0 ? z.x : z.y);
                z = cmul(z, w);
            }
        }
        __syncthreads();   // Q (and on pass 0, P) ready

        // ----- Mainloop: 4 k8 steps; A columns offset by 32*pass -----
        const int pbase = 32 * pass;
        #pragma unroll
        for (int ks = 0; ks < 4; ks++) {
            const int kb = 8 * ks;
            u32 a[2][4];
            #pragma unroll
            for (int mt = 0; mt < 2; mt++) {
                int r0 = (16 * mt + g) * QP + pbase + kb;
                int r1 = r0 + 8 * QP;
                a[mt][0] = sP[r0 + t];
                a[mt][1] = sP[r1 + t];
                a[mt][2] = sP[r0 + t + 4];
                a[mt][3] = sP[r1 + t + 4];
            }
            u32 b[4][2];
            #pragma unroll
            for (int nt = 0; nt < 4; nt++) {
                int ib = (32 * wid + 8 * nt + g) * QQ + kb;
                b[nt][0] = sQ[ib + t];
                b[nt][1] = sQ[ib + t + 4];
            }
            #pragma unroll
            for (int mt = 0; mt < 2; mt++)
                #pragma unroll
                for (int nt = 0; nt < 4; nt++)
                    mma_tf32(acc[mt][nt], a[mt], b[nt]);
        }
        __syncthreads();   // done reading sQ before pass-1 overwrites it
    }

    // ---------- Epilogue: D[j,i] -> out[h, j*128 + i], float2 stores ----------
    float* op = out + (size_t)h * (size_t)L;
    #pragma unroll
    for (int mt = 0; mt < 2; mt++) {
        #pragma unroll
        for (int nt = 0; nt < 4; nt++) {
            int j0 = 16 * mt + g;
            int i0 = 32 * wid + 8 * nt + 2 * t;
            *(float2*)&op[j0 * TT + i0]       = make_float2(acc[mt][nt][0], acc[mt][nt][1]);
            *(float2*)&op[(j0 + 8) * TT + i0] = make_float2(acc[mt][nt][2], acc[mt][nt][3]);
        }
    }
}

extern "C" void kernel_launch(void* const* d_in, const int* in_sizes, int n_in,
                              void* d_out, int out_size) {
    // inputs: [0]=L (scalar), [1]=log_dt (H), [2]=C (H,32,2),
    //         [3]=log_A_real (H,32), [4]=A_imag (H,32)
    const float* log_dt = (const float*)d_in[1];
    const float* C      = (const float*)d_in[2];
    const float* lAr    = (const float*)d_in[3];
    const float* Aim    = (const float*)d_in[4];
    float* out = (float*)d_out;

    int H = in_sizes[1];          // 1024
    int L = out_size / H;         // 4096

    cudaFuncSetAttribute(s4d_mma_kernel,
                         cudaFuncAttributeMaxDynamicSharedMemorySize, SMEM_B);
    s4d_mma_kernel<<<H, NTH, SMEM_B>>>(log_dt, C, lAr, Aim, out, L);
}